// round 4
// baseline (speedup 1.0000x reference)
#include <cuda_runtime.h>
#include <cstdint>
#include <math.h>

#define D    128
#define S_MAX 125000
#define EPS  1e-13f

// Scratch (static device globals -- no allocation)
__device__ float g_y[(size_t)S_MAX * D];   // 64 MB: per-segment normalized weighted sum of x
__device__ float g_sg[S_MAX];              // per-segment sum of normalized gates
__device__ int   g_starts[S_MAX + 1];      // segment start offsets

// ---------------------------------------------------------------------------
// Kernel 1: segment start offsets from the sorted index array (int4 scan).
// Each thread handles 4 elements; writes starts at value transitions.
// ---------------------------------------------------------------------------
__global__ void seg_starts_kernel(const int* __restrict__ idx, int N, int S) {
    int t  = blockIdx.x * blockDim.x + threadIdx.x;
    int n0 = t * 4;
    if (n0 >= N) return;

    int v0, v1, v2, v3;
    if (n0 + 3 < N) {
        int4 c = *(const int4*)(idx + n0);
        v0 = c.x; v1 = c.y; v2 = c.z; v3 = c.w;
    } else {
        v0 = idx[n0];
        v1 = (n0 + 1 < N) ? idx[n0 + 1] : v0;
        v2 = (n0 + 2 < N) ? idx[n0 + 2] : v1;
        v3 = (n0 + 3 < N) ? idx[n0 + 3] : v2;
    }
    int prev = (n0 == 0) ? -1 : idx[n0 - 1];

    int vals[4] = {v0, v1, v2, v3};
    #pragma unroll
    for (int j = 0; j < 4; ++j) {
        if (n0 + j < N) {
            int cur = vals[j];
            for (int s = prev + 1; s <= cur; ++s) g_starts[s] = n0 + j;
            prev = cur;
        }
    }
    if (n0 + 4 >= N) {   // thread containing the last element fills the tail
        for (int s = prev + 1; s <= S; ++s) g_starts[s] = N;
    }
}

// ---- packed f32x2 helpers (FFMA2 only reachable via PTX fma.rn.f32x2) ----
__device__ __forceinline__ void fma2(unsigned long long& d,
                                     unsigned long long a,
                                     unsigned long long b,
                                     unsigned long long c) {
    asm("fma.rn.f32x2 %0, %1, %2, %3;" : "=l"(d) : "l"(a), "l"(b), "l"(c));
}
__device__ __forceinline__ float2 unpack2(unsigned long long u) {
    float2 f;
    asm("mov.b64 {%0, %1}, %2;" : "=f"(f.x), "=f"(f.y) : "l"(u));
    return f;
}
__device__ __forceinline__ unsigned long long pack2(float lo, float hi) {
    unsigned long long u;
    asm("mov.b64 %0, {%1, %2};" : "=l"(u) : "f"(lo), "f"(hi));
    return u;
}

// ---------------------------------------------------------------------------
// Kernel 2: single-pass fused gate + weighted segment aggregation.
//   y_s = (Sum_r g_r x_r) / denom,  g_r = w_r exp(x_r.Wg + bg)
// One warp per segment. Lane = (grp[2b], sub[3b]):
//   - group grp (8 lanes) owns row base+grp of each 4-row batch
//   - lane sub covers interleaved float4 chunks {sub, sub+8, sub+16, sub+24}
//     -> each load instruction is 128B contiguous per row (coalesced)
// Gate dot reduces over 8 lanes (3 SHFL per 4 rows, 1 MUFU per 4 rows).
// Cross-group butterfly (xor 8,16) once per segment.
// All dot/accumulate math in packed f32x2 (half the FFMA issues).
// ---------------------------------------------------------------------------
__global__ void __launch_bounds__(256)
agg_kernel(const float* __restrict__ x,
           const float* __restrict__ w,
           const float* __restrict__ Wg,
           const float* __restrict__ bgp,
           int S) {
    int warp = (int)((blockIdx.x * (unsigned)blockDim.x + threadIdx.x) >> 5);
    if (warp >= S) return;
    int lane = threadIdx.x & 31;
    int grp  = lane >> 3;      // 0..3 : row within batch
    int sub  = lane & 7;       // 0..7 : chunk class

    int r0  = g_starts[warp];
    int len = g_starts[warp + 1] - r0;

    // Wg chunks for this lane (4 float4 = 8 packed f32x2)
    ulonglong2 wg[4];
    #pragma unroll
    for (int j = 0; j < 4; ++j)
        wg[j] = *(const ulonglong2*)(Wg + (sub + 8 * j) * 4);
    float bg0 = bgp[0];

    ulonglong2 acc[4];
    #pragma unroll
    for (int j = 0; j < 4; ++j) { acc[j].x = 0ull; acc[j].y = 0ull; }   // {0.f,0.f}
    float denom = 0.f;

    for (int base = 0; base < len; base += 4) {
        int  r     = base + grp;
        bool valid = (r < len);

        ulonglong2 v[4];
        float wr = 0.f;
        if (valid) {
            const float* xp = x + (size_t)(r0 + r) * D;
            #pragma unroll
            for (int j = 0; j < 4; ++j)
                v[j] = *(const ulonglong2*)(xp + (sub + 8 * j) * 4);
            wr = w[r0 + r];
        } else {
            #pragma unroll
            for (int j = 0; j < 4; ++j) { v[j].x = 0ull; v[j].y = 0ull; }
        }

        // packed partial dot over this lane's 16 elements
        unsigned long long d = 0ull;
        #pragma unroll
        for (int j = 0; j < 4; ++j) {
            fma2(d, v[j].x, wg[j].x, d);
            fma2(d, v[j].y, wg[j].y, d);
        }
        float2 dh = unpack2(d);
        float  p  = dh.x + dh.y;
        // reduce over the 8 lanes of this group (masks 1,2,4 stay in-group)
        p += __shfl_xor_sync(0xffffffffu, p, 1);
        p += __shfl_xor_sync(0xffffffffu, p, 2);
        p += __shfl_xor_sync(0xffffffffu, p, 4);

        float g = wr * __expf(p + bg0);
        denom += g;

        unsigned long long g2 = pack2(g, g);
        #pragma unroll
        for (int j = 0; j < 4; ++j) {
            fma2(acc[j].x, g2, v[j].x, acc[j].x);
            fma2(acc[j].y, g2, v[j].y, acc[j].y);
        }
    }

    // cross-group combine: sum lanes {l, l^8, l^16, l^24} (one per group)
    float a[16];
    #pragma unroll
    for (int j = 0; j < 4; ++j) {
        float2 lo = unpack2(acc[j].x);
        float2 hi = unpack2(acc[j].y);
        a[4 * j + 0] = lo.x; a[4 * j + 1] = lo.y;
        a[4 * j + 2] = hi.x; a[4 * j + 3] = hi.y;
    }
    #pragma unroll
    for (int i = 0; i < 16; ++i) {
        a[i] += __shfl_xor_sync(0xffffffffu, a[i], 8);
        a[i] += __shfl_xor_sync(0xffffffffu, a[i], 16);
    }
    denom += __shfl_xor_sync(0xffffffffu, denom, 8);
    denom += __shfl_xor_sync(0xffffffffu, denom, 16);

    float inv = 1.f / (denom + EPS);
    if (lane < 8) {   // group 0 writes all chunks (8 lanes x 4 float4 = 128 floats)
        float* yb = g_y + (size_t)warp * D;
        #pragma unroll
        for (int j = 0; j < 4; ++j) {
            float4 o;
            o.x = a[4 * j + 0] * inv; o.y = a[4 * j + 1] * inv;
            o.z = a[4 * j + 2] * inv; o.w = a[4 * j + 3] * inv;
            *(float4*)(yb + (sub + 8 * j) * 4) = o;
        }
    }
    if (lane == 0) g_sg[warp] = denom * inv;
}

// ---------------------------------------------------------------------------
// Kernel 3: out[S,128] = y @ Wm + sg (x) bm    (tf32 mma.sync, fp32 accum)
// ---------------------------------------------------------------------------
#define BM 128
#define BN 128
#define BK 32

__device__ __forceinline__ uint32_t f2tf32(float f) {
    uint32_t r;
    asm("cvt.rna.tf32.f32 %0, %1;" : "=r"(r) : "f"(f));
    return r;
}

__device__ __forceinline__ void mma_tf32(float* c, const uint32_t* a, const uint32_t* b) {
    asm volatile(
        "mma.sync.aligned.m16n8k8.row.col.f32.tf32.tf32.f32 "
        "{%0,%1,%2,%3}, {%4,%5,%6,%7}, {%8,%9}, {%0,%1,%2,%3};\n"
        : "+f"(c[0]), "+f"(c[1]), "+f"(c[2]), "+f"(c[3])
        : "r"(a[0]), "r"(a[1]), "r"(a[2]), "r"(a[3]), "r"(b[0]), "r"(b[1]));
}

__global__ void __launch_bounds__(256)
gemm_kernel(const float* __restrict__ Wm,
            const float* __restrict__ bm,
            float* __restrict__ out, int S) {
    __shared__ float yS[BM][BK + 4];
    __shared__ float wS[BK][BN + 4];

    int tid  = threadIdx.x;
    int wid  = tid >> 5;
    int lane = tid & 31;
    int warp_m = wid & 3;
    int warp_n = wid >> 2;
    int grp = lane >> 2;
    int tg  = lane & 3;
    int rowbase = blockIdx.x * BM;

    float c[2][8][4];
    #pragma unroll
    for (int mf = 0; mf < 2; ++mf)
        #pragma unroll
        for (int nf = 0; nf < 8; ++nf)
            #pragma unroll
            for (int i = 0; i < 4; ++i) c[mf][nf][i] = 0.f;

    for (int kt = 0; kt < D; kt += BK) {
        __syncthreads();
        {
            int r = tid >> 3;
            int q = tid & 7;
            #pragma unroll
            for (int it = 0; it < 4; ++it) {
                int row  = r + it * 32;
                int grow = rowbase + row;
                float4 v = make_float4(0.f,0.f,0.f,0.f);
                if (grow < S)
                    v = *(const float4*)(g_y + (size_t)grow * D + kt + q * 4);
                *(float4*)&yS[row][q * 4] = v;
            }
            int k = tid >> 3;
            #pragma unroll
            for (int it = 0; it < 4; ++it) {
                int qq = (tid & 7) + it * 8;
                *(float4*)&wS[k][qq * 4] =
                    *(const float4*)(Wm + (size_t)(kt + k) * D + qq * 4);
            }
        }
        __syncthreads();

        #pragma unroll
        for (int ks = 0; ks < BK; ks += 8) {
            uint32_t a[2][4];
            uint32_t b[8][2];
            #pragma unroll
            for (int mf = 0; mf < 2; ++mf) {
                int r = warp_m * 32 + mf * 16;
                a[mf][0] = f2tf32(yS[r + grp    ][ks + tg    ]);
                a[mf][1] = f2tf32(yS[r + grp + 8][ks + tg    ]);
                a[mf][2] = f2tf32(yS[r + grp    ][ks + tg + 4]);
                a[mf][3] = f2tf32(yS[r + grp + 8][ks + tg + 4]);
            }
            #pragma unroll
            for (int nf = 0; nf < 8; ++nf) {
                int col = warp_n * 64 + nf * 8 + grp;
                b[nf][0] = f2tf32(wS[ks + tg    ][col]);
                b[nf][1] = f2tf32(wS[ks + tg + 4][col]);
            }
            #pragma unroll
            for (int mf = 0; mf < 2; ++mf)
                #pragma unroll
                for (int nf = 0; nf < 8; ++nf)
                    mma_tf32(c[mf][nf], a[mf], b[nf]);
        }
    }

    #pragma unroll
    for (int mf = 0; mf < 2; ++mf) {
        int row0 = rowbase + warp_m * 32 + mf * 16 + grp;
        int row1 = row0 + 8;
        float sgA = (row0 < S) ? g_sg[row0] : 0.f;
        float sgB = (row1 < S) ? g_sg[row1] : 0.f;
        #pragma unroll
        for (int nf = 0; nf < 8; ++nf) {
            int col = warp_n * 64 + nf * 8 + tg * 2;
            float b0 = bm[col], b1 = bm[col + 1];
            if (row0 < S) {
                float2 o;
                o.x = c[mf][nf][0] + sgA * b0;
                o.y = c[mf][nf][1] + sgA * b1;
                *(float2*)(out + (size_t)row0 * D + col) = o;
            }
            if (row1 < S) {
                float2 o;
                o.x = c[mf][nf][2] + sgB * b0;
                o.y = c[mf][nf][3] + sgB * b1;
                *(float2*)(out + (size_t)row1 * D + col) = o;
            }
        }
    }
}

// ---------------------------------------------------------------------------
extern "C" void kernel_launch(void* const* d_in, const int* in_sizes, int n_in,
                              void* d_out, int out_size) {
    const float* x   = (const float*)d_in[0];
    const int*   idx = (const int*)  d_in[1];
    const float* w   = (const float*)d_in[2];
    const float* Wg  = (const float*)d_in[3];
    const float* bg  = (const float*)d_in[4];
    const float* Wm  = (const float*)d_in[5];
    const float* bm  = (const float*)d_in[6];
    float* out = (float*)d_out;

    int N = in_sizes[1];
    int S = out_size / D;

    int quads = (N + 3) / 4;
    seg_starts_kernel<<<(quads + 255) / 256, 256>>>(idx, N, S);

    long long total_threads = (long long)S * 32;
    int agg_blocks = (int)((total_threads + 255) / 256);
    agg_kernel<<<agg_blocks, 256>>>(x, w, Wg, bg, S);

    gemm_kernel<<<(S + BM - 1) / BM, 256>>>(Wm, bm, out, S);
}

// round 6
// speedup vs baseline: 1.1542x; 1.1542x over previous
#include <cuda_runtime.h>
#include <cstdint>
#include <math.h>

#define D    128
#define S_MAX 125000
#define EPS  1e-13f

// Scratch (static device globals -- no allocation)
__device__ float g_y[(size_t)S_MAX * D];   // 64 MB: per-segment normalized weighted sum of x
__device__ float g_sg[S_MAX];              // per-segment sum of normalized gates
__device__ int   g_starts[S_MAX + 1];      // segment start offsets

// ---------------------------------------------------------------------------
// Kernel 1: segment start offsets from the sorted index array (int4 scan).
// ---------------------------------------------------------------------------
__global__ void seg_starts_kernel(const int* __restrict__ idx, int N, int S) {
    int t  = blockIdx.x * blockDim.x + threadIdx.x;
    int n0 = t * 4;
    if (n0 >= N) return;

    int v0, v1, v2, v3;
    if (n0 + 3 < N) {
        int4 c = *(const int4*)(idx + n0);
        v0 = c.x; v1 = c.y; v2 = c.z; v3 = c.w;
    } else {
        v0 = idx[n0];
        v1 = (n0 + 1 < N) ? idx[n0 + 1] : v0;
        v2 = (n0 + 2 < N) ? idx[n0 + 2] : v1;
        v3 = (n0 + 3 < N) ? idx[n0 + 3] : v2;
    }
    int prev = (n0 == 0) ? -1 : idx[n0 - 1];

    int vals[4] = {v0, v1, v2, v3};
    #pragma unroll
    for (int j = 0; j < 4; ++j) {
        if (n0 + j < N) {
            int cur = vals[j];
            for (int s = prev + 1; s <= cur; ++s) g_starts[s] = n0 + j;
            prev = cur;
        }
    }
    if (n0 + 4 >= N) {
        for (int s = prev + 1; s <= S; ++s) g_starts[s] = N;
    }
}

__device__ __forceinline__ float dot4(float4 a, float4 b) {
    return a.x * b.x + a.y * b.y + a.z * b.z + a.w * b.w;
}

// ---------------------------------------------------------------------------
// Kernel 2: single-pass fused gate + weighted segment aggregation.
//   y_s = (Sum_r g_r x_r) / denom,  g_r = w_r exp(x_r.Wg + bg)
//
// One warp per segment. Lane l owns columns [4l, 4l+4) for the WHOLE kernel
// (acc never crosses lanes; epilogue is a single full-warp STG.128).
// Per 4-row batch, quadrant q = lane>>3 "owns" row base+q. Each lane loads
// rows in XOR-permuted order v_m = x[base + (q^m)], which makes the 4
// simultaneous dot reductions cost only 6 shuffles (2x mask8 + 1x mask16
// redistribution, then 3 in-quadrant butterflies) and the gate broadcast a
// static pairing g_m = shfl_xor(g, 8m) <-> v_m.  1 MUFU per batch (own row).
// ---------------------------------------------------------------------------
__global__ void __launch_bounds__(256)
agg_kernel(const float* __restrict__ x,
           const float* __restrict__ w,
           const float* __restrict__ Wg,
           const float* __restrict__ bgp,
           int S) {
    int warp = (int)((blockIdx.x * (unsigned)blockDim.x + threadIdx.x) >> 5);
    if (warp >= S) return;
    int lane = threadIdx.x & 31;
    int q    = lane >> 3;                 // quadrant: owns row base+q

    int r0  = g_starts[warp];
    int len = g_starts[warp + 1] - r0;

    float4 wg  = *(const float4*)(Wg + lane * 4);
    float  bg0 = bgp[0];
    const float* xb = x + (size_t)r0 * D + lane * 4;

    int pm1 = q ^ 1, pm2 = q ^ 2, pm3 = q ^ 3;   // permuted row slots

    float4 acc = make_float4(0.f, 0.f, 0.f, 0.f);
    float  denom = 0.f;                   // per-quadrant partial

    for (int base = 0; base < len; base += 4) {
        int rA = base + q;                // own row
        int rB = base + pm1;
        int rC = base + pm2;
        int rD = base + pm3;

        float4 v0 = make_float4(0.f,0.f,0.f,0.f), v1 = v0, v2 = v0, v3 = v0;
        if (rA < len) v0 = *(const float4*)(xb + (size_t)rA * D);
        if (rB < len) v1 = *(const float4*)(xb + (size_t)rB * D);
        if (rC < len) v2 = *(const float4*)(xb + (size_t)rC * D);
        if (rD < len) v3 = *(const float4*)(xb + (size_t)rD * D);
        float wr = (rA < len) ? w[r0 + rA] : 0.f;

        // partial dots: p_m = <v_m, wg> = partial of row base+(q^m) at cols 4l
        float p0 = dot4(v0, wg);
        float p1 = dot4(v1, wg);
        float p2 = dot4(v2, wg);
        float p3 = dot4(v3, wg);

        // redistribute + reduce: quadrant q ends with row base+q's full dot
        float t01 = p0 + __shfl_xor_sync(0xffffffffu, p1, 8);
        float t23 = p2 + __shfl_xor_sync(0xffffffffu, p3, 8);
        float t   = t01 + __shfl_xor_sync(0xffffffffu, t23, 16);
        t += __shfl_xor_sync(0xffffffffu, t, 1);
        t += __shfl_xor_sync(0xffffffffu, t, 2);
        t += __shfl_xor_sync(0xffffffffu, t, 4);

        float g = wr * __expf(t + bg0);   // gate of own row (0 if invalid)
        denom += g;

        // static broadcast: g_m = gate of row base+(q^m), pairs with v_m
        float g1 = __shfl_xor_sync(0xffffffffu, g, 8);
        float g2 = __shfl_xor_sync(0xffffffffu, g, 16);
        float g3 = __shfl_xor_sync(0xffffffffu, g, 24);

        acc.x += g * v0.x + g1 * v1.x + g2 * v2.x + g3 * v3.x;
        acc.y += g * v0.y + g1 * v1.y + g2 * v2.y + g3 * v3.y;
        acc.z += g * v0.z + g1 * v1.z + g2 * v2.z + g3 * v3.z;
        acc.w += g * v0.w + g1 * v1.w + g2 * v2.w + g3 * v3.w;
    }

    // combine per-quadrant denoms (lanes within a quadrant agree)
    denom += __shfl_xor_sync(0xffffffffu, denom, 8);
    denom += __shfl_xor_sync(0xffffffffu, denom, 16);

    float inv = 1.f / (denom + EPS);
    float4 o;
    o.x = acc.x * inv; o.y = acc.y * inv;
    o.z = acc.z * inv; o.w = acc.w * inv;
    *(float4*)(g_y + (size_t)warp * D + lane * 4) = o;
    if (lane == 0) g_sg[warp] = denom * inv;
}

// ---------------------------------------------------------------------------
// Kernel 3: out[S,128] = y @ Wm + sg (x) bm    (tf32 mma.sync, fp32 accum)
// ---------------------------------------------------------------------------
#define BM 128
#define BN 128
#define BK 32

__device__ __forceinline__ uint32_t f2tf32(float f) {
    uint32_t r;
    asm("cvt.rna.tf32.f32 %0, %1;" : "=r"(r) : "f"(f));
    return r;
}

__device__ __forceinline__ void mma_tf32(float* c, const uint32_t* a, const uint32_t* b) {
    asm volatile(
        "mma.sync.aligned.m16n8k8.row.col.f32.tf32.tf32.f32 "
        "{%0,%1,%2,%3}, {%4,%5,%6,%7}, {%8,%9}, {%0,%1,%2,%3};\n"
        : "+f"(c[0]), "+f"(c[1]), "+f"(c[2]), "+f"(c[3])
        : "r"(a[0]), "r"(a[1]), "r"(a[2]), "r"(a[3]), "r"(b[0]), "r"(b[1]));
}

__global__ void __launch_bounds__(256)
gemm_kernel(const float* __restrict__ Wm,
            const float* __restrict__ bm,
            float* __restrict__ out, int S) {
    __shared__ float yS[BM][BK + 4];
    __shared__ float wS[BK][BN + 4];

    int tid  = threadIdx.x;
    int wid  = tid >> 5;
    int lane = tid & 31;
    int warp_m = wid & 3;
    int warp_n = wid >> 2;
    int grp = lane >> 2;
    int tg  = lane & 3;
    int rowbase = blockIdx.x * BM;

    float c[2][8][4];
    #pragma unroll
    for (int mf = 0; mf < 2; ++mf)
        #pragma unroll
        for (int nf = 0; nf < 8; ++nf)
            #pragma unroll
            for (int i = 0; i < 4; ++i) c[mf][nf][i] = 0.f;

    for (int kt = 0; kt < D; kt += BK) {
        __syncthreads();
        {
            int r = tid >> 3;
            int qq = tid & 7;
            #pragma unroll
            for (int it = 0; it < 4; ++it) {
                int row  = r + it * 32;
                int grow = rowbase + row;
                float4 v = make_float4(0.f,0.f,0.f,0.f);
                if (grow < S)
                    v = *(const float4*)(g_y + (size_t)grow * D + kt + qq * 4);
                *(float4*)&yS[row][qq * 4] = v;
            }
            int k = tid >> 3;
            #pragma unroll
            for (int it = 0; it < 4; ++it) {
                int q2 = (tid & 7) + it * 8;
                *(float4*)&wS[k][q2 * 4] =
                    *(const float4*)(Wm + (size_t)(kt + k) * D + q2 * 4);
            }
        }
        __syncthreads();

        #pragma unroll
        for (int ks = 0; ks < BK; ks += 8) {
            uint32_t a[2][4];
            uint32_t b[8][2];
            #pragma unroll
            for (int mf = 0; mf < 2; ++mf) {
                int r = warp_m * 32 + mf * 16;
                a[mf][0] = f2tf32(yS[r + grp    ][ks + tg    ]);
                a[mf][1] = f2tf32(yS[r + grp + 8][ks + tg    ]);
                a[mf][2] = f2tf32(yS[r + grp    ][ks + tg + 4]);
                a[mf][3] = f2tf32(yS[r + grp + 8][ks + tg + 4]);
            }
            #pragma unroll
            for (int nf = 0; nf < 8; ++nf) {
                int col = warp_n * 64 + nf * 8 + grp;
                b[nf][0] = f2tf32(wS[ks + tg    ][col]);
                b[nf][1] = f2tf32(wS[ks + tg + 4][col]);
            }
            #pragma unroll
            for (int mf = 0; mf < 2; ++mf)
                #pragma unroll
                for (int nf = 0; nf < 8; ++nf)
                    mma_tf32(c[mf][nf], a[mf], b[nf]);
        }
    }

    #pragma unroll
    for (int mf = 0; mf < 2; ++mf) {
        int row0 = rowbase + warp_m * 32 + mf * 16 + grp;
        int row1 = row0 + 8;
        float sgA = (row0 < S) ? g_sg[row0] : 0.f;
        float sgB = (row1 < S) ? g_sg[row1] : 0.f;
        #pragma unroll
        for (int nf = 0; nf < 8; ++nf) {
            int col = warp_n * 64 + nf * 8 + tg * 2;
            float b0 = bm[col], b1 = bm[col + 1];
            if (row0 < S) {
                float2 o;
                o.x = c[mf][nf][0] + sgA * b0;
                o.y = c[mf][nf][1] + sgA * b1;
                *(float2*)(out + (size_t)row0 * D + col) = o;
            }
            if (row1 < S) {
                float2 o;
                o.x = c[mf][nf][2] + sgB * b0;
                o.y = c[mf][nf][3] + sgB * b1;
                *(float2*)(out + (size_t)row1 * D + col) = o;
            }
        }
    }
}

// ---------------------------------------------------------------------------
extern "C" void kernel_launch(void* const* d_in, const int* in_sizes, int n_in,
                              void* d_out, int out_size) {
    const float* x   = (const float*)d_in[0];
    const int*   idx = (const int*)  d_in[1];
    const float* w   = (const float*)d_in[2];
    const float* Wg  = (const float*)d_in[3];
    const float* bg  = (const float*)d_in[4];
    const float* Wm  = (const float*)d_in[5];
    const float* bm  = (const float*)d_in[6];
    float* out = (float*)d_out;

    int N = in_sizes[1];
    int S = out_size / D;

    int quads = (N + 3) / 4;
    seg_starts_kernel<<<(quads + 255) / 256, 256>>>(idx, N, S);

    long long total_threads = (long long)S * 32;
    int agg_blocks = (int)((total_threads + 255) / 256);
    agg_kernel<<<agg_blocks, 256>>>(x, w, Wg, bg, S);

    gemm_kernel<<<(S + BM - 1) / BM, 256>>>(Wm, bm, out, S);
}